// round 10
// baseline (speedup 1.0000x reference)
#include <cuda_runtime.h>

// stepSSM fused kernel, R9: single graph node, fully packed float2 smem consts.
//  - No __constant__, no memcpy nodes, no uniform LDGs (R6's 5 memcpy nodes
//    cost ~12us replay; R7's uniform LDGs cost l1tex + registers; R8's
//    symbol-address plumbing risked capture failure).
//  - Per (layer i, quad q): 10 float2 slots packed contiguously:
//      0: (A r0,i0)  1: (A r1,i1)  2: (B r0,i0)  3: (B r1,i1)
//      4: (C r0,i0)  5: (C r1,i1)  6: (fw00,fw01) 7: (fw10,fw11)
//      8: (fb0,fb1)  9: (D[i,hd], 0)
//    q-stride = 20 words -> per-slot the 4 q addresses hit bank pairs
//    {0,1},{20,21},{8,9},{28,29}: conflict-free, single wavefront each.
//  - Tail [160..167]: fc1_w (4), fc1_b (1), fc10 w (2), fc10 b (1), broadcast.
//  - 48 LDS.64/thread total, zero scalar LDS; 4 threads/row, fully coalesced
//    float4 streaming state I/O (established R3/R6 mapping).
//
// Inputs (metadata order):
//   0: x[B,4]  1: states[4,B,2,4,2]  2: fc1_w[2,4]  3: fc1_b[2]
//   4: fc_w[5,2,2]  5: fc_b[5,2]  6: A[4,2,4,2]  7: Bm[4,2,4,2]
//   8: C[4,1,2,4,2]  9: D[4,1,2]
// Output: h[B,2] ++ new_states[4,B,2,4,2]  (f32)

#define THREADS 256
#define N_PAIRS 168   // 160 per-(i,q) + 8 broadcast tail

__global__ __launch_bounds__(THREADS) void step_ssm_kernel(
    const float4* __restrict__ x,        // [B]
    const float4* __restrict__ states,   // [4*B*4] float4
    const float*  __restrict__ fc1_w,    // 8
    const float*  __restrict__ fc1_b,    // 2
    const float*  __restrict__ fc_w,     // 20
    const float*  __restrict__ fc_b,     // 10
    const float*  __restrict__ A,        // 64
    const float*  __restrict__ Bm,       // 64
    const float*  __restrict__ C,        // 64
    const float*  __restrict__ D,        // 8
    float2*       __restrict__ out_h,      // [B]
    float4*       __restrict__ out_states, // [4*B*4] float4
    int B)
{
    __shared__ float2 sp[N_PAIRS];
    {
        int t = threadIdx.x;
        if (t < 160) {
            int i = t / 40, rem = t % 40;
            int qq = rem / 10, slot = rem % 10;
            int lb = i * 16 + qq * 4;
            float2 v;
            switch (slot) {
                case 0: v = make_float2(A [lb + 0], A [lb + 1]); break;
                case 1: v = make_float2(A [lb + 2], A [lb + 3]); break;
                case 2: v = make_float2(Bm[lb + 0], Bm[lb + 1]); break;
                case 3: v = make_float2(Bm[lb + 2], Bm[lb + 3]); break;
                case 4: v = make_float2(C [lb + 0], C [lb + 1]); break;
                case 5: v = make_float2(C [lb + 2], C [lb + 3]); break;
                case 6: v = make_float2(fc_w[i * 4 + 0], fc_w[i * 4 + 1]); break;
                case 7: v = make_float2(fc_w[i * 4 + 2], fc_w[i * 4 + 3]); break;
                case 8: v = make_float2(fc_b[i * 2 + 0], fc_b[i * 2 + 1]); break;
                default: v = make_float2(D[i * 2 + (qq >> 1)], 0.0f); break;
            }
            sp[t] = v;
        } else if (t < N_PAIRS) {
            float2 v;
            switch (t - 160) {
                case 0: v = make_float2(fc1_w[0], fc1_w[1]); break;
                case 1: v = make_float2(fc1_w[2], fc1_w[3]); break;
                case 2: v = make_float2(fc1_w[4], fc1_w[5]); break;
                case 3: v = make_float2(fc1_w[6], fc1_w[7]); break;
                case 4: v = make_float2(fc1_b[0], fc1_b[1]); break;
                case 5: v = make_float2(fc_w[16], fc_w[17]); break;
                case 6: v = make_float2(fc_w[18], fc_w[19]); break;
                default: v = make_float2(fc_b[8], fc_b[9]); break;
            }
            sp[t] = v;
        }
    }
    __syncthreads();

    const int t   = blockIdx.x * blockDim.x + threadIdx.x;
    const int row = t >> 2;
    const int q   = t & 3;
    if (row >= B) return;

    const size_t layer_str = (size_t)B * 4;   // float4 units
    const size_t my_off    = (size_t)row * 4 + q;

    // front-load all global reads
    float4 st[4];
#pragma unroll
    for (int i = 0; i < 4; i++)
        st[i] = __ldcs(states + (size_t)i * layer_str + my_off);
    float4 xv = __ldg(x + row);

    // fc1 from broadcast float2 slots
    float2 wa = sp[160], wb = sp[161], wc = sp[162], wd = sp[163], bb = sp[164];
    float h0 = fmaf(xv.x, wa.x, fmaf(xv.y, wa.y, fmaf(xv.z, wb.x, fmaf(xv.w, wb.y, bb.x))));
    float h1 = fmaf(xv.x, wc.x, fmaf(xv.y, wc.y, fmaf(xv.z, wd.x, fmaf(xv.w, wd.y, bb.y))));

    const int hd = q >> 1;

#pragma unroll
    for (int i = 0; i < 4; i++) {
        const int base = (i * 4 + q) * 10;
        float2 a0 = sp[base + 0], a1 = sp[base + 1];
        float2 b0 = sp[base + 2], b1 = sp[base + 3];
        float2 c0 = sp[base + 4], c1 = sp[base + 5];
        float2 f0 = sp[base + 6], f1 = sp[base + 7];
        float2 fb = sp[base + 8];
        float  dd = sp[base + 9].x;

        const float u = (hd == 0) ? h0 : h1;

        float nr0 = fmaf(a0.x, st[i].x, fmaf(-a0.y, st[i].y, b0.x * u));
        float ni0 = fmaf(a0.x, st[i].y, fmaf( a0.y, st[i].x, b0.y * u));
        float nr1 = fmaf(a1.x, st[i].z, fmaf(-a1.y, st[i].w, b1.x * u));
        float ni1 = fmaf(a1.x, st[i].w, fmaf( a1.y, st[i].z, b1.y * u));

        __stcs(out_states + (size_t)i * layer_str + my_off,
               make_float4(nr0, ni0, nr1, ni1));

        // partial C-projection (2 f's), reduce within head pair, swap heads
        float acc = fmaf(c0.x, nr0, fmaf(-c0.y, ni0,
                    fmaf(c1.x, nr1, -c1.y * ni1)));
        acc += __shfl_xor_sync(0xFFFFFFFFu, acc, 1);

        float y = fmaf(2.0f, acc, u * dd);
        y = (y >= 0.0f) ? y : 0.125f * y;
        float yo = __shfl_xor_sync(0xFFFFFFFFu, y, 2);
        float y0 = (hd == 0) ? y  : yo;
        float y1 = (hd == 0) ? yo : y;

        h0 = fmaf(y0, f0.x, fmaf(y1, f0.y, fb.x));
        h1 = fmaf(y0, f1.x, fmaf(y1, f1.y, fb.y));
    }

    // fc10 — lane q==0 writes the contiguous float2
    if (q == 0) {
        float2 p0 = sp[165], p1 = sp[166], pb = sp[167];
        float o0 = fmaf(h0, p0.x, fmaf(h1, p0.y, pb.x));
        float o1 = fmaf(h0, p1.x, fmaf(h1, p1.y, pb.y));
        out_h[row] = make_float2(o0, o1);
    }
}

extern "C" void kernel_launch(void* const* d_in, const int* in_sizes, int n_in,
                              void* d_out, int out_size)
{
    const float* x     = (const float*)d_in[0];
    const float* states= (const float*)d_in[1];
    const float* fc1_w = (const float*)d_in[2];
    const float* fc1_b = (const float*)d_in[3];
    const float* fc_w  = (const float*)d_in[4];
    const float* fc_b  = (const float*)d_in[5];
    const float* A     = (const float*)d_in[6];
    const float* Bm    = (const float*)d_in[7];
    const float* C     = (const float*)d_in[8];
    const float* D     = (const float*)d_in[9];

    int B = in_sizes[0] / 4;  // x is [B,4]

    float*  out = (float*)d_out;
    float2* oh  = (float2*)out;                   // h: [B,2]
    float4* ost = (float4*)(out + (size_t)2 * B); // new_states: [4,B,2,4,2]

    long long total = (long long)B * 4;           // 4 threads per row
    int grid = (int)((total + THREADS - 1) / THREADS);
    step_ssm_kernel<<<grid, THREADS>>>(
        (const float4*)x, (const float4*)states,
        fc1_w, fc1_b, fc_w, fc_b, A, Bm, C, D,
        oh, ost, B);
}

// round 11
// speedup vs baseline: 1.0432x; 1.0432x over previous
#include <cuda_runtime.h>

// stepSSM fused kernel, R10: single graph node; R6 kernel body with the
// uniform weights read via warp-BROADCAST vector LDS instead of LDCU.
//
// Wavefront model (calibrated on R3/R4/R6/R7/R9): vector LDS with k distinct
// addresses per warp costs ~k crossbar phases; broadcast LDS of any width is
// 1 phase. So:
//   - q-distinct A/Bm/C: float2 pairs (6 per layer, ~2 phases each)  [as R6]
//   - warp-uniform fc1_w/fc1_b/fc_w/fc_b/D: broadcast float4/float2 (1 phase
//     each, 17 total) — replaces R6's const-port reads without its 5 memcpy
//     nodes (~12us replay tax) and avoids R7's LDG l1tex/register blowup.
//   - 4 threads/row, coalesced float4 streaming state I/O (established).
//
// Inputs (metadata order):
//   0: x[B,4]  1: states[4,B,2,4,2]  2: fc1_w[2,4]  3: fc1_b[2]
//   4: fc_w[5,2,2]  5: fc_b[5,2]  6: A[4,2,4,2]  7: Bm[4,2,4,2]
//   8: C[4,1,2,4,2]  9: D[4,1,2]
// Output: h[B,2] ++ new_states[4,B,2,4,2]  (f32)

#define THREADS 256

__global__ __launch_bounds__(THREADS) void step_ssm_kernel(
    const float4* __restrict__ x,        // [B]
    const float4* __restrict__ states,   // [4*B*4] float4
    const float*  __restrict__ fc1_w,    // 8
    const float*  __restrict__ fc1_b,    // 2
    const float*  __restrict__ fc_w,     // 20
    const float*  __restrict__ fc_b,     // 10
    const float*  __restrict__ A,        // 64
    const float*  __restrict__ Bm,       // 64
    const float*  __restrict__ C,        // 64
    const float*  __restrict__ D,        // 8
    float2*       __restrict__ out_h,      // [B]
    float4*       __restrict__ out_states, // [4*B*4] float4
    int B)
{
    // q-distinct constants: [0..31]=A, [32..63]=Bm, [64..95]=C as float2
    // pairs; pair index for (layer i, quad q, pair j): v = i*8 + q*2 + j.
    __shared__ float2 sABC[96];
    // warp-uniform weights (broadcast reads):
    __shared__ float4 sFW[5];   // fc_w rows 0..4 (fc3,5,7,9,10)
    __shared__ float2 sFB[5];   // fc_b rows
    __shared__ float2 sD[4];    // D per layer: (D[i,0], D[i,1])
    __shared__ float4 sF1W[2];  // fc1_w
    __shared__ float2 sF1B;     // fc1_b

    {
        int t = threadIdx.x;
        if (t < 96) {
            const float* src = (t < 32) ? A : (t < 64) ? Bm : C;
            int v = t & 31;
            sABC[t] = make_float2(src[2 * v], src[2 * v + 1]);
        } else if (t < 101) {        // 5x fc_w float4
            int i = t - 96;
            sFW[i] = make_float4(fc_w[i*4+0], fc_w[i*4+1], fc_w[i*4+2], fc_w[i*4+3]);
        } else if (t < 106) {        // 5x fc_b float2
            int i = t - 101;
            sFB[i] = make_float2(fc_b[i*2+0], fc_b[i*2+1]);
        } else if (t < 110) {        // 4x D float2
            int i = t - 106;
            sD[i] = make_float2(D[i*2+0], D[i*2+1]);
        } else if (t < 112) {        // 2x fc1_w float4
            int i = t - 110;
            sF1W[i] = make_float4(fc1_w[i*4+0], fc1_w[i*4+1], fc1_w[i*4+2], fc1_w[i*4+3]);
        } else if (t == 112) {
            sF1B = make_float2(fc1_b[0], fc1_b[1]);
        }
    }
    __syncthreads();

    const int t   = blockIdx.x * blockDim.x + threadIdx.x;
    const int row = t >> 2;
    const int q   = t & 3;
    if (row >= B) return;

    const size_t layer_str = (size_t)B * 4;   // float4 units
    const size_t my_off    = (size_t)row * 4 + q;

    // front-load all global reads
    float4 st[4];
#pragma unroll
    for (int i = 0; i < 4; i++)
        st[i] = __ldcs(states + (size_t)i * layer_str + my_off);
    float4 xv = __ldg(x + row);

    // fc1 — broadcast float4/float2 LDS (1 wavefront each)
    float4 w0 = sF1W[0], w1 = sF1W[1];
    float2 b1 = sF1B;
    float h0 = fmaf(xv.x, w0.x, fmaf(xv.y, w0.y, fmaf(xv.z, w0.z, fmaf(xv.w, w0.w, b1.x))));
    float h1 = fmaf(xv.x, w1.x, fmaf(xv.y, w1.y, fmaf(xv.z, w1.z, fmaf(xv.w, w1.w, b1.y))));

    const int hd = q >> 1;
    const int vq = q * 2;

#pragma unroll
    for (int i = 0; i < 4; i++) {
        const int v = i * 8 + vq;
        float2 a0 = sABC[v],      a1 = sABC[v + 1];
        float2 b0 = sABC[32 + v], b2 = sABC[32 + v + 1];
        float2 c0 = sABC[64 + v], c1 = sABC[64 + v + 1];

        const float u = (hd == 0) ? h0 : h1;

        float nr0 = fmaf(a0.x, st[i].x, fmaf(-a0.y, st[i].y, b0.x * u));
        float ni0 = fmaf(a0.x, st[i].y, fmaf( a0.y, st[i].x, b0.y * u));
        float nr1 = fmaf(a1.x, st[i].z, fmaf(-a1.y, st[i].w, b2.x * u));
        float ni1 = fmaf(a1.x, st[i].w, fmaf( a1.y, st[i].z, b2.y * u));

        __stcs(out_states + (size_t)i * layer_str + my_off,
               make_float4(nr0, ni0, nr1, ni1));

        // partial C-projection (2 f's), reduce within head pair, swap heads
        float acc = fmaf(c0.x, nr0, fmaf(-c0.y, ni0,
                    fmaf(c1.x, nr1, -c1.y * ni1)));
        acc += __shfl_xor_sync(0xFFFFFFFFu, acc, 1);

        float2 dp = sD[i];                       // broadcast
        float y = fmaf(2.0f, acc, u * ((hd == 0) ? dp.x : dp.y));
        y = (y >= 0.0f) ? y : 0.125f * y;
        float yo = __shfl_xor_sync(0xFFFFFFFFu, y, 2);
        float y0 = (hd == 0) ? y  : yo;
        float y1 = (hd == 0) ? yo : y;

        float4 fw = sFW[i];                      // broadcast
        float2 fb = sFB[i];                      // broadcast
        h0 = fmaf(y0, fw.x, fmaf(y1, fw.y, fb.x));
        h1 = fmaf(y0, fw.z, fmaf(y1, fw.w, fb.y));
    }

    // fc10 — lane q==0 writes the contiguous float2
    if (q == 0) {
        float4 fw = sFW[4];
        float2 fb = sFB[4];
        float o0 = fmaf(h0, fw.x, fmaf(h1, fw.y, fb.x));
        float o1 = fmaf(h0, fw.z, fmaf(h1, fw.w, fb.y));
        out_h[row] = make_float2(o0, o1);
    }
}

extern "C" void kernel_launch(void* const* d_in, const int* in_sizes, int n_in,
                              void* d_out, int out_size)
{
    const float* x     = (const float*)d_in[0];
    const float* states= (const float*)d_in[1];
    const float* fc1_w = (const float*)d_in[2];
    const float* fc1_b = (const float*)d_in[3];
    const float* fc_w  = (const float*)d_in[4];
    const float* fc_b  = (const float*)d_in[5];
    const float* A     = (const float*)d_in[6];
    const float* Bm    = (const float*)d_in[7];
    const float* C     = (const float*)d_in[8];
    const float* D     = (const float*)d_in[9];

    int B = in_sizes[0] / 4;  // x is [B,4]

    float*  out = (float*)d_out;
    float2* oh  = (float2*)out;                   // h: [B,2]
    float4* ost = (float4*)(out + (size_t)2 * B); // new_states: [4,B,2,4,2]

    long long total = (long long)B * 4;           // 4 threads per row
    int grid = (int)((total + THREADS - 1) / THREADS);
    step_ssm_kernel<<<grid, THREADS>>>(
        (const float4*)x, (const float4*)states,
        fc1_w, fc1_b, fc_w, fc_b, A, Bm, C, D,
        oh, ost, B);
}

// round 12
// speedup vs baseline: 1.0675x; 1.0232x over previous
#include <cuda_runtime.h>

// stepSSM fused kernel, R11 = R8 re-bench (R8's run died to container infra,
// never measured). Rationale: across 8 measured kernels the causal limiter is
// occupancy (registers), not l1tex wavefronts. Only the __constant__ path
// keeps weights in uniform registers (zero GPR cost) -> 32 regs, occ 87%,
// DRAM 79.6%, kernel 80.4us (R6). R6's flaw was 5 memcpy nodes (~12us replay
// tax); this design needs only 2 extra nodes:
//   node 1: pack kernel gathers the 48 uniform weights into __device__ staging
//   node 2: ONE 192B cudaMemcpyToSymbolAsync D2D -> __constant__ cst
//   node 3: main kernel (exact R6 body, best measured)
//
// Inputs (metadata order):
//   0: x[B,4]  1: states[4,B,2,4,2]  2: fc1_w[2,4]  3: fc1_b[2]
//   4: fc_w[5,2,2]  5: fc_b[5,2]  6: A[4,2,4,2]  7: Bm[4,2,4,2]
//   8: C[4,1,2,4,2]  9: D[4,1,2]
// Output: h[B,2] ++ new_states[4,B,2,4,2]  (f32)

#define THREADS 256

// __constant__ layout (floats)
#define CC_FC1W 0    // 8
#define CC_FC1B 8    // 2
#define CC_FCW  10   // 20
#define CC_FCB  30   // 10
#define CC_D    40   // 8
#define CC_N    48

__constant__ float cst[CC_N];
__device__ float g_stage[CC_N];

__global__ void pack_consts_kernel(
    const float* __restrict__ fc1_w,
    const float* __restrict__ fc1_b,
    const float* __restrict__ fc_w,
    const float* __restrict__ fc_b,
    const float* __restrict__ D)
{
    int t = threadIdx.x;
    if (t < CC_N) {
        float v;
        if      (t < CC_FC1B) v = fc1_w[t - CC_FC1W];
        else if (t < CC_FCW)  v = fc1_b[t - CC_FC1B];
        else if (t < CC_FCB)  v = fc_w [t - CC_FCW];
        else if (t < CC_D)    v = fc_b [t - CC_FCB];
        else                  v = D    [t - CC_D];
        g_stage[t] = v;
    }
}

__global__ __launch_bounds__(THREADS) void step_ssm_kernel(
    const float4* __restrict__ x,        // [B]
    const float4* __restrict__ states,   // [4*B*4] float4
    const float*  __restrict__ A,
    const float*  __restrict__ Bm,
    const float*  __restrict__ C,
    float2*       __restrict__ out_h,      // [B]
    float4*       __restrict__ out_states, // [4*B*4] float4
    int B)
{
    // sABC: [0..31]=A, [32..63]=Bm, [64..95]=C as float2 pairs.
    // pair index for (layer i, quad q, pair j): v = i*8 + q*2 + j.
    __shared__ float2 sABC[96];
    {
        int t = threadIdx.x;
        if (t < 96) {
            const float* src = (t < 32) ? A : (t < 64) ? Bm : C;
            int v = t & 31;
            sABC[t] = make_float2(src[2 * v], src[2 * v + 1]);
        }
    }
    __syncthreads();

    const int t   = blockIdx.x * blockDim.x + threadIdx.x;
    const int row = t >> 2;
    const int q   = t & 3;
    if (row >= B) return;

    const size_t layer_str = (size_t)B * 4;   // float4 units
    const size_t my_off    = (size_t)row * 4 + q;

    // front-load all global reads
    float4 st[4];
#pragma unroll
    for (int i = 0; i < 4; i++)
        st[i] = __ldcs(states + (size_t)i * layer_str + my_off);
    float4 xv = __ldg(x + row);

    // fc1 (uniform consts -> LDCU on the const port: zero l1tex, zero GPRs)
    float h0 = fmaf(xv.x, cst[CC_FC1W + 0], fmaf(xv.y, cst[CC_FC1W + 1],
               fmaf(xv.z, cst[CC_FC1W + 2], fmaf(xv.w, cst[CC_FC1W + 3], cst[CC_FC1B + 0]))));
    float h1 = fmaf(xv.x, cst[CC_FC1W + 4], fmaf(xv.y, cst[CC_FC1W + 5],
               fmaf(xv.z, cst[CC_FC1W + 6], fmaf(xv.w, cst[CC_FC1W + 7], cst[CC_FC1B + 1]))));

    const int hd = q >> 1;
    const int vq = q * 2;

#pragma unroll
    for (int i = 0; i < 4; i++) {
        const int v = i * 8 + vq;
        float2 a0 = sABC[v],      a1 = sABC[v + 1];
        float2 b0 = sABC[32 + v], b1 = sABC[32 + v + 1];
        float2 c0 = sABC[64 + v], c1 = sABC[64 + v + 1];

        const float u = (hd == 0) ? h0 : h1;

        float nr0 = fmaf(a0.x, st[i].x, fmaf(-a0.y, st[i].y, b0.x * u));
        float ni0 = fmaf(a0.x, st[i].y, fmaf( a0.y, st[i].x, b0.y * u));
        float nr1 = fmaf(a1.x, st[i].z, fmaf(-a1.y, st[i].w, b1.x * u));
        float ni1 = fmaf(a1.x, st[i].w, fmaf( a1.y, st[i].z, b1.y * u));

        __stcs(out_states + (size_t)i * layer_str + my_off,
               make_float4(nr0, ni0, nr1, ni1));

        // partial C-projection (2 f's), reduce within head pair, swap heads
        float acc = fmaf(c0.x, nr0, fmaf(-c0.y, ni0,
                    fmaf(c1.x, nr1, -c1.y * ni1)));
        acc += __shfl_xor_sync(0xFFFFFFFFu, acc, 1);

        float y = fmaf(2.0f, acc, u * cst[CC_D + i * 2 + hd]);
        y = (y >= 0.0f) ? y : 0.125f * y;
        float yo = __shfl_xor_sync(0xFFFFFFFFu, y, 2);
        float y0 = (hd == 0) ? y  : yo;
        float y1 = (hd == 0) ? yo : y;

        const int wb = CC_FCW + i * 4;
        h0 = fmaf(y0, cst[wb + 0], fmaf(y1, cst[wb + 1], cst[CC_FCB + i * 2 + 0]));
        h1 = fmaf(y0, cst[wb + 2], fmaf(y1, cst[wb + 3], cst[CC_FCB + i * 2 + 1]));
    }

    // fc10 — lane q==0 writes the contiguous float2
    if (q == 0) {
        const int wb = CC_FCW + 16;
        float o0 = fmaf(h0, cst[wb + 0], fmaf(h1, cst[wb + 1], cst[CC_FCB + 8]));
        float o1 = fmaf(h0, cst[wb + 2], fmaf(h1, cst[wb + 3], cst[CC_FCB + 9]));
        out_h[row] = make_float2(o0, o1);
    }
}

extern "C" void kernel_launch(void* const* d_in, const int* in_sizes, int n_in,
                              void* d_out, int out_size)
{
    const float* x     = (const float*)d_in[0];
    const float* states= (const float*)d_in[1];
    const float* fc1_w = (const float*)d_in[2];
    const float* fc1_b = (const float*)d_in[3];
    const float* fc_w  = (const float*)d_in[4];
    const float* fc_b  = (const float*)d_in[5];
    const float* A     = (const float*)d_in[6];
    const float* Bm    = (const float*)d_in[7];
    const float* C     = (const float*)d_in[8];
    const float* D     = (const float*)d_in[9];

    // node 1: gather scattered uniform weights into contiguous staging
    pack_consts_kernel<<<1, 64>>>(fc1_w, fc1_b, fc_w, fc_b, D);

    // node 2: single 192B D2D memcpy into the constant bank
    void* stage_addr = nullptr;
    cudaGetSymbolAddress(&stage_addr, g_stage);   // host-side query, capture-safe
    cudaMemcpyToSymbolAsync(cst, stage_addr, CC_N * sizeof(float), 0,
                            cudaMemcpyDeviceToDevice, 0);

    int B = in_sizes[0] / 4;  // x is [B,4]

    float*  out = (float*)d_out;
    float2* oh  = (float2*)out;                   // h: [B,2]
    float4* ost = (float4*)(out + (size_t)2 * B); // new_states: [4,B,2,4,2]

    // node 3: main kernel
    long long total = (long long)B * 4;           // 4 threads per row
    int grid = (int)((total + THREADS - 1) / THREADS);
    step_ssm_kernel<<<grid, THREADS>>>(
        (const float4*)x, (const float4*)states, A, Bm, C,
        oh, ost, B);
}

// round 13
// speedup vs baseline: 1.0762x; 1.0082x over previous
#include <cuda_runtime.h>
#include <cstdint>

// stepSSM fused kernel, R12: ONE graph node, R6-class register pressure.
//
// Calibrated facts: R11 kernel = 79.8us (32 regs, occ 85%, DRAM 80.2%) but
// each extra graph node costs ~3.5us replay -> multi-node designs cap at
// ~86.8 total. Single-node designs so far bloat to 43-47 regs because ptxas
// HOISTS the (provably-constant) smem weight loads and keeps them live for
// the whole body, halving occupancy (R3/R7/R10: occ ~54%, DRAM <=76%).
//
// Fix: read the 48 warp-uniform weights from shared via asm-volatile
// ld.shared.f32 at each use site. Volatile asm cannot be hoisted/duplicated,
// so each weight lives in a GPR only for its consuming FMA. All reads are
// warp-broadcast (1 l1tex wavefront each; R3 sustained 2x this count).
// A/Bm/C stay as q-distinct float2 pairs (proven in R6/R11).
//
// Inputs (metadata order):
//   0: x[B,4]  1: states[4,B,2,4,2]  2: fc1_w[2,4]  3: fc1_b[2]
//   4: fc_w[5,2,2]  5: fc_b[5,2]  6: A[4,2,4,2]  7: Bm[4,2,4,2]
//   8: C[4,1,2,4,2]  9: D[4,1,2]
// Output: h[B,2] ++ new_states[4,B,2,4,2]  (f32)

#define THREADS 256

// weight staging layout in shared (floats)
#define CW_FC1W 0    // 8
#define CW_FC1B 8    // 2
#define CW_FCW  10   // 20
#define CW_FCB  30   // 10
#define CW_D    40   // 8
#define CW_N    48

// un-hoistable broadcast shared read, compile-time offset
template <int OFF>
__device__ __forceinline__ float ldsw(uint32_t base) {
    float v;
    asm volatile("ld.shared.f32 %0, [%1+%2];" : "=f"(v) : "r"(base), "n"(OFF * 4));
    return v;
}
// runtime-offset variant (for the hd-dependent D read)
__device__ __forceinline__ float ldsw_dyn(uint32_t addr) {
    float v;
    asm volatile("ld.shared.f32 %0, [%1];" : "=f"(v) : "r"(addr));
    return v;
}

__global__ __launch_bounds__(THREADS) void step_ssm_kernel(
    const float4* __restrict__ x,        // [B]
    const float4* __restrict__ states,   // [4*B*4] float4
    const float*  __restrict__ fc1_w,    // 8
    const float*  __restrict__ fc1_b,    // 2
    const float*  __restrict__ fc_w,     // 20
    const float*  __restrict__ fc_b,     // 10
    const float*  __restrict__ A,        // 64
    const float*  __restrict__ Bm,       // 64
    const float*  __restrict__ C,        // 64
    const float*  __restrict__ D,        // 8
    float2*       __restrict__ out_h,      // [B]
    float4*       __restrict__ out_states, // [4*B*4] float4
    int B)
{
    // q-distinct A/Bm/C as float2 pairs: v = i*8 + q*2 + j  (R6 layout)
    __shared__ float2 sABC[96];
    __shared__ float  sw[CW_N];
    {
        int t = threadIdx.x;
        if (t < 96) {
            const float* src = (t < 32) ? A : (t < 64) ? Bm : C;
            int v = t & 31;
            sABC[t] = make_float2(src[2 * v], src[2 * v + 1]);
        } else if (t < 96 + CW_N) {
            int u = t - 96;
            float v;
            if      (u < CW_FC1B) v = fc1_w[u - CW_FC1W];
            else if (u < CW_FCW)  v = fc1_b[u - CW_FC1B];
            else if (u < CW_FCB)  v = fc_w [u - CW_FCW];
            else if (u < CW_D)    v = fc_b [u - CW_FCB];
            else                  v = D    [u - CW_D];
            sw[u] = v;
        }
    }
    __syncthreads();

    uint32_t swb;
    {
        asm("{ .reg .u64 t0; cvta.to.shared.u64 t0, %1; cvt.u32.u64 %0, t0; }"
            : "=r"(swb) : "l"(sw));
    }

    const int t   = blockIdx.x * blockDim.x + threadIdx.x;
    const int row = t >> 2;
    const int q   = t & 3;
    if (row >= B) return;

    const size_t layer_str = (size_t)B * 4;   // float4 units
    const size_t my_off    = (size_t)row * 4 + q;

    // front-load all global reads
    float4 st[4];
#pragma unroll
    for (int i = 0; i < 4; i++)
        st[i] = __ldcs(states + (size_t)i * layer_str + my_off);
    float4 xv = __ldg(x + row);

    // fc1 — broadcast volatile LDS per use (no hoisting)
    float h0 = fmaf(xv.x, ldsw<CW_FC1W + 0>(swb), fmaf(xv.y, ldsw<CW_FC1W + 1>(swb),
               fmaf(xv.z, ldsw<CW_FC1W + 2>(swb), fmaf(xv.w, ldsw<CW_FC1W + 3>(swb),
                    ldsw<CW_FC1B + 0>(swb)))));
    float h1 = fmaf(xv.x, ldsw<CW_FC1W + 4>(swb), fmaf(xv.y, ldsw<CW_FC1W + 5>(swb),
               fmaf(xv.z, ldsw<CW_FC1W + 6>(swb), fmaf(xv.w, ldsw<CW_FC1W + 7>(swb),
                    ldsw<CW_FC1B + 1>(swb)))));

    const int hd = q >> 1;
    const int vq = q * 2;
    const uint32_t dbase = swb + (CW_D + hd) * 4;   // + i*8 bytes per layer

#pragma unroll
    for (int i = 0; i < 4; i++) {
        const int v = i * 8 + vq;
        float2 a0 = sABC[v],      a1 = sABC[v + 1];
        float2 b0 = sABC[32 + v], b1 = sABC[32 + v + 1];
        float2 c0 = sABC[64 + v], c1 = sABC[64 + v + 1];

        const float u = (hd == 0) ? h0 : h1;

        float nr0 = fmaf(a0.x, st[i].x, fmaf(-a0.y, st[i].y, b0.x * u));
        float ni0 = fmaf(a0.x, st[i].y, fmaf( a0.y, st[i].x, b0.y * u));
        float nr1 = fmaf(a1.x, st[i].z, fmaf(-a1.y, st[i].w, b1.x * u));
        float ni1 = fmaf(a1.x, st[i].w, fmaf( a1.y, st[i].z, b1.y * u));

        __stcs(out_states + (size_t)i * layer_str + my_off,
               make_float4(nr0, ni0, nr1, ni1));

        // partial C-projection (2 f's), reduce within head pair, swap heads
        float acc = fmaf(c0.x, nr0, fmaf(-c0.y, ni0,
                    fmaf(c1.x, nr1, -c1.y * ni1)));
        acc += __shfl_xor_sync(0xFFFFFFFFu, acc, 1);

        float y = fmaf(2.0f, acc, u * ldsw_dyn(dbase + i * 8));
        y = (y >= 0.0f) ? y : 0.125f * y;
        float yo = __shfl_xor_sync(0xFFFFFFFFu, y, 2);
        float y0 = (hd == 0) ? y  : yo;
        float y1 = (hd == 0) ? yo : y;

        h0 = fmaf(y0, ldsw<CW_FCW + 0>(swb + i * 16), fmaf(y1, ldsw<CW_FCW + 1>(swb + i * 16),
                  ldsw_dyn(swb + (CW_FCB + i * 2 + 0) * 4)));
        h1 = fmaf(y0, ldsw<CW_FCW + 2>(swb + i * 16), fmaf(y1, ldsw<CW_FCW + 3>(swb + i * 16),
                  ldsw_dyn(swb + (CW_FCB + i * 2 + 1) * 4)));
    }

    // fc10 — lane q==0 writes the contiguous float2
    if (q == 0) {
        float o0 = fmaf(h0, ldsw<CW_FCW + 16>(swb), fmaf(h1, ldsw<CW_FCW + 17>(swb),
                        ldsw<CW_FCB + 8>(swb)));
        float o1 = fmaf(h0, ldsw<CW_FCW + 18>(swb), fmaf(h1, ldsw<CW_FCW + 19>(swb),
                        ldsw<CW_FCB + 9>(swb)));
        out_h[row] = make_float2(o0, o1);
    }
}

extern "C" void kernel_launch(void* const* d_in, const int* in_sizes, int n_in,
                              void* d_out, int out_size)
{
    const float* x     = (const float*)d_in[0];
    const float* states= (const float*)d_in[1];
    const float* fc1_w = (const float*)d_in[2];
    const float* fc1_b = (const float*)d_in[3];
    const float* fc_w  = (const float*)d_in[4];
    const float* fc_b  = (const float*)d_in[5];
    const float* A     = (const float*)d_in[6];
    const float* Bm    = (const float*)d_in[7];
    const float* C     = (const float*)d_in[8];
    const float* D     = (const float*)d_in[9];

    int B = in_sizes[0] / 4;  // x is [B,4]

    float*  out = (float*)d_out;
    float2* oh  = (float2*)out;                   // h: [B,2]
    float4* ost = (float4*)(out + (size_t)2 * B); // new_states: [4,B,2,4,2]

    long long total = (long long)B * 4;           // 4 threads per row
    int grid = (int)((total + THREADS - 1) / THREADS);
    step_ssm_kernel<<<grid, THREADS>>>(
        (const float4*)x, (const float4*)states,
        fc1_w, fc1_b, fc_w, fc_b, A, Bm, C, D,
        oh, ost, B);
}